// round 14
// baseline (speedup 1.0000x reference)
#include <cuda_runtime.h>
#include <cstdint>

#define Bb   128
#define Lq   128
#define Iin  256
#define Hh   256
#define G4   1024
#define Kd   512

#define OUT_ELEMS (Bb*Lq*Hh)
#define HF_OFF (OUT_ELEMS)
#define CF_OFF (OUT_ELEMS + 2*Bb*Hh)
#define KL_OFF (OUT_ELEMS + 4*Bb*Hh)

// -------- scratch --------
__device__ float g_std0[G4*Kd];   // pexp(0.5*logvar)
__device__ float g_std1[G4*Kd];
__device__ float g_bstd0[G4], g_bstd1[G4];
__device__ float g_h0[Lq*Bb*Hh];
__device__ float g_c0[Bb*Hh];
__device__ float g_c1[Bb*Hh];

__device__ const float* g_pwmu0;
__device__ const float* g_pwlv0;
__device__ const float* g_pwmu1;
__device__ const float* g_pwlv1;
__device__ const float* g_pbmu0;
__device__ const float* g_pblv0;
__device__ const float* g_pbmu1;
__device__ const float* g_pblv1;

// ---- Cephes/XLA pexp: fma-contracted, clamp +-88.3762626647949 (m in [-127,127]) ----
__device__ __forceinline__ float pexp_fma(float x) {
    x = fminf(fmaxf(x, -88.3762626647949f), 88.3762626647949f);
    float m = floorf(fmaf(x, 1.44269504088896341f, 0.5f));
    float r = fmaf(m, -0.693359375f, x);
    r = fmaf(m, 2.12194440e-4f, r);
    float r2 = __fmul_rn(r, r);
    float p = 1.9875691500e-4f;
    p = fmaf(p, r, 1.3981999507e-3f);
    p = fmaf(p, r, 8.3334519073e-3f);
    p = fmaf(p, r, 4.1665795894e-2f);
    p = fmaf(p, r, 1.6666665459e-1f);
    p = fmaf(p, r, 5.0000001201e-1f);
    p = fmaf(p, r2, r);
    p = __fadd_rn(p, 1.0f);
    int mi = (int)m;                               // guaranteed [-127, 127]
    return __fmul_rn(p, __int_as_float((mi + 127) << 23));
}

// ---- Eigen ptanh: rational poly, fma-contracted, clamp 7.99881172180175781 ----
#define CLAMP_E 7.99881172180175781f
__device__ __forceinline__ float ptanh(float x) {
    float ax = fabsf(x);
    if (ax < 0.0004f) return x;
    float cx = fminf(fmaxf(x, -CLAMP_E), CLAMP_E);
    float x2 = __fmul_rn(cx, cx);
    float np = -2.76076847742355e-16f;
    np = fmaf(x2, np, 2.00018790482477e-13f);
    np = fmaf(x2, np, -8.60467152213735e-11f);
    np = fmaf(x2, np, 5.12229709037114e-08f);
    np = fmaf(x2, np, 1.48572235717979e-05f);
    np = fmaf(x2, np, 6.37261928875436e-04f);
    np = fmaf(x2, np, 4.89352455891786e-03f);
    np = __fmul_rn(cx, np);
    float dp = 1.19825839466702e-06f;
    dp = fmaf(x2, dp, 1.18534705686654e-04f);
    dp = fmaf(x2, dp, 2.26843463243900e-03f);
    dp = fmaf(x2, dp, 4.89352518554385e-03f);
    return __fdiv_rn(np, dp);
}

// ---- logistic = 1 / (1 + pexp(-x)) ----
__device__ __forceinline__ float plogistic(float v) {
    float e = pexp_fma(__fmul_rn(-1.0f, v));
    return __fdiv_rn(1.0f, __fadd_rn(1.0f, e));
}

// ============ probe: resolve mu/logvar layout from bias zero-pattern ============
__global__ void probe_kernel(const float* b0, const float* b1,
                             const float* b2, const float* b3,
                             const float* w0, const float* w1,
                             const float* w2, const float* w3) {
    if (threadIdx.x != 0 || blockIdx.x != 0) return;
    const float* bs[4] = {b0, b1, b2, b3};
    const float* wsrc[4] = {w0, w1, w2, w3};
    bool isMu[4];
    int nmu = 0;
    for (int i = 0; i < 4; i++) {
        bool z = true;
        for (int k = 0; k < 16; k++) z = z && (bs[i][k] == 0.0f);
        isMu[i] = z;
        if (z) nmu++;
    }
    int muSlot[2], lvSlot[2];
    if (nmu == 2) {
        int a = 0, c = 0;
        for (int i = 0; i < 4; i++) {
            if (isMu[i]) muSlot[a++] = i; else lvSlot[c++] = i;
        }
    } else {
        muSlot[0] = 0; lvSlot[0] = 1; muSlot[1] = 2; lvSlot[1] = 3;
    }
    g_pbmu0 = bs[muSlot[0]]; g_pbmu1 = bs[muSlot[1]];
    g_pblv0 = bs[lvSlot[0]]; g_pblv1 = bs[lvSlot[1]];
    g_pwmu0 = wsrc[muSlot[0]]; g_pwmu1 = wsrc[muSlot[1]];
    g_pwlv0 = wsrc[lvSlot[0]]; g_pwlv1 = wsrc[lvSlot[1]];
}

// ============ precompute: std = pexp(0.5*lv) ============
__global__ void pre_kernel(float* out) {
    const float* wlv0 = g_pwlv0;
    const float* wlv1 = g_pwlv1;
    const float* blv0 = g_pblv0;
    const float* blv1 = g_pblv1;
    int idx = blockIdx.x * blockDim.x + threadIdx.x;
    int stride = gridDim.x * blockDim.x;
    for (int i = idx; i < G4*Kd; i += stride) {
        g_std0[i] = pexp_fma(__fmul_rn(0.5f, wlv0[i]));
        g_std1[i] = pexp_fma(__fmul_rn(0.5f, wlv1[i]));
    }
    for (int i = idx; i < G4; i += stride) {
        g_bstd0[i] = pexp_fma(__fmul_rn(0.5f, blv0[i]));
        g_bstd1[i] = pexp_fma(__fmul_rn(0.5f, blv1[i]));
    }
    for (int i = idx; i < Bb*Hh; i += stride) { g_c0[i] = 0.f; g_c1[i] = 0.f; }
    if (idx == 0) out[KL_OFF] = 0.f;
}

// ============ KL reduction (order-insensitive; loose tolerance) ============
__global__ void kl_kernel(float* out) {
    const float* wmu0 = g_pwmu0; const float* wlv0 = g_pwlv0;
    const float* wmu1 = g_pwmu1; const float* wlv1 = g_pwlv1;
    const float* bmu0 = g_pbmu0; const float* blv0 = g_pblv0;
    const float* bmu1 = g_pbmu1; const float* blv1 = g_pblv1;
    int idx = blockIdx.x * blockDim.x + threadIdx.x;
    int stride = gridDim.x * blockDim.x;
    float acc = 0.f;
    for (int i = idx; i < G4*Kd; i += stride) {
        float m = wmu0[i], v = wlv0[i]; acc += m*m + pexp_fma(v) - v;
        m = wmu1[i]; v = wlv1[i];       acc += m*m + pexp_fma(v) - v;
    }
    for (int i = idx; i < G4; i += stride) {
        float m = bmu0[i], v = blv0[i]; acc += m*m + pexp_fma(v) - v;
        m = bmu1[i]; v = blv1[i];       acc += m*m + pexp_fma(v) - v;
    }
    acc *= 0.5f;
    for (int o = 16; o; o >>= 1) acc += __shfl_down_sync(0xffffffffu, acc, o);
    __shared__ float sred[8];
    int lane = threadIdx.x & 31, w = threadIdx.x >> 5;
    if (lane == 0) sred[w] = acc;
    __syncthreads();
    if (w == 0) {
        acc = (lane < (int)(blockDim.x >> 5)) ? sred[lane] : 0.f;
        for (int o = 4; o; o >>= 1) acc += __shfl_down_sync(0xffffffffu, acc, o);
        if (lane == 0) atomicAdd(&out[KL_OFF], acc);
    }
}

// ============ skewed step kernel: frozen Eigen/XLA bundle ============
// Arithmetic per output element (FROZEN — bit-exact vs reference):
//   w   = fmaf(eps, std, mu)
//   acc = sequential fmaf chain, k ascending 0..511
//   z   = __fadd_rn(acc, fmaf(eps_b, bstd, bmu))
//   i,f,o = 1/(1+pexp(-z));  g = ptanh(z)
//   c'  = fmaf(f, c, __fmul_rn(i, g));  h = __fmul_rn(o, ptanh(c'))
__global__ void __launch_bounds__(128) step_kernel(
    int t,
    const float* __restrict__ x,
    const float* __restrict__ epsw0, const float* __restrict__ epsb0,
    const float* __restrict__ epsw1, const float* __restrict__ epsb1,
    float* __restrict__ out)
{
    const int layer = blockIdx.y;
    if (layer == 0 && t >= Lq) return;
    if (layer == 1 && t == 0) return;
    const int s = layer ? (t - 1) : t;

    const float* wmu  = layer ? g_pwmu1 : g_pwmu0;
    const float* bmu  = layer ? g_pbmu1 : g_pbmu0;
    const float* epsw = layer ? epsw1   : epsw0;
    const float* epsb = layer ? epsb1   : epsb0;
    const float* stdw = layer ? g_std1  : g_std0;
    const float* bstd = layer ? g_bstd1 : g_bstd0;
    float* cst = layer ? g_c1 : g_c0;

    const int j = blockIdx.x;
    const int b = threadIdx.x;

    __shared__ float ws[4][128];

    const float* srcLo;
    const float* srcHi;
    if (layer == 0) {
        srcLo = x + ((size_t)b*Lq + t)*Iin;
        srcHi = (t > 0) ? (g_h0 + ((size_t)(t-1)*Bb + b)*Hh) : nullptr;
    } else {
        srcLo = g_h0 + ((size_t)s*Bb + b)*Hh;
        srcHi = (s > 0) ? (out + ((size_t)b*Lq + (s-1))*Hh) : nullptr;
    }

    float a0 = 0.f, a1 = 0.f, a2 = 0.f, a3 = 0.f;

    #pragma unroll
    for (int kc = 0; kc < Kd; kc += 128) {
        #pragma unroll
        for (int g = 0; g < 4; g++) {
            int row = g*Hh + j;
            int wi  = row*Kd + kc + b;
            size_t eo = ((size_t)s*G4 + row)*Kd + kc + b;
            ws[g][b] = fmaf(epsw[eo], stdw[wi], wmu[wi]);
        }
        __syncthreads();

        const float* src = (kc < Iin) ? srcLo : srcHi;
        const int base = (kc < Iin) ? kc : (kc - Iin);
        if (src != nullptr) {
            #pragma unroll
            for (int k = 0; k < 128; k += 4) {
                float4 a4 = *reinterpret_cast<const float4*>(src + base + k);
                a0 = fmaf(a4.x, ws[0][k+0], a0);
                a1 = fmaf(a4.x, ws[1][k+0], a1);
                a2 = fmaf(a4.x, ws[2][k+0], a2);
                a3 = fmaf(a4.x, ws[3][k+0], a3);
                a0 = fmaf(a4.y, ws[0][k+1], a0);
                a1 = fmaf(a4.y, ws[1][k+1], a1);
                a2 = fmaf(a4.y, ws[2][k+1], a2);
                a3 = fmaf(a4.y, ws[3][k+1], a3);
                a0 = fmaf(a4.z, ws[0][k+2], a0);
                a1 = fmaf(a4.z, ws[1][k+2], a1);
                a2 = fmaf(a4.z, ws[2][k+2], a2);
                a3 = fmaf(a4.z, ws[3][k+2], a3);
                a0 = fmaf(a4.w, ws[0][k+3], a0);
                a1 = fmaf(a4.w, ws[1][k+3], a1);
                a2 = fmaf(a4.w, ws[2][k+3], a2);
                a3 = fmaf(a4.w, ws[3][k+3], a3);
            }
        }
        __syncthreads();
    }

    float zi = __fadd_rn(a0, fmaf(epsb[(size_t)s*G4 + 0*Hh + j], bstd[0*Hh + j], bmu[0*Hh + j]));
    float zf = __fadd_rn(a1, fmaf(epsb[(size_t)s*G4 + 1*Hh + j], bstd[1*Hh + j], bmu[1*Hh + j]));
    float zg = __fadd_rn(a2, fmaf(epsb[(size_t)s*G4 + 2*Hh + j], bstd[2*Hh + j], bmu[2*Hh + j]));
    float zo = __fadd_rn(a3, fmaf(epsb[(size_t)s*G4 + 3*Hh + j], bstd[3*Hh + j], bmu[3*Hh + j]));

    float ig = plogistic(zi);
    float fg = plogistic(zf);
    float gg = ptanh(zg);
    float og = plogistic(zo);

    int ci = b*Hh + j;
    float cn = fmaf(fg, cst[ci], __fmul_rn(ig, gg));
    cst[ci] = cn;
    float h = __fmul_rn(og, ptanh(cn));

    if (layer == 0) g_h0[((size_t)t*Bb + b)*Hh + j] = h;
    else            out [((size_t)b*Lq + s)*Hh + j] = h;
}

// ============ finalize ============
__global__ void final_kernel(float* out) {
    int idx = blockIdx.x * blockDim.x + threadIdx.x;
    if (idx < Bb*Hh) {
        int b = idx / Hh, j = idx % Hh;
        out[HF_OFF + idx]           = g_h0[((size_t)(Lq-1)*Bb)*Hh + idx];
        out[HF_OFF + Bb*Hh + idx]   = out[((size_t)b*Lq + (Lq-1))*Hh + j];
        out[CF_OFF + idx]           = g_c0[idx];
        out[CF_OFF + Bb*Hh + idx]   = g_c1[idx];
    }
}

// ============ launch ============
extern "C" void kernel_launch(void* const* d_in, const int* in_sizes, int n_in,
                              void* d_out, int out_size) {
    int xi = -1, wg[4], bg[4], ewg[2], ebg[2];
    int nw = 0, nb = 0, ne = 0, nber = 0;
    for (int i = 0; i < n_in; i++) {
        int sz = in_sizes[i];
        if (sz == Bb*Lq*Iin)            xi = i;
        else if (sz == G4*Kd)           { if (nw < 4)   wg[nw++]   = i; }
        else if (sz == G4)              { if (nb < 4)   bg[nb++]   = i; }
        else if (sz == Lq*G4*Kd)        { if (ne < 2)   ewg[ne++]  = i; }
        else if (sz == Lq*G4)           { if (nber < 2) ebg[nber++] = i; }
    }

    const float* x     = (const float*)d_in[xi];
    const float* epsw0 = (const float*)d_in[ewg[0]];
    const float* epsw1 = (const float*)d_in[ewg[1]];
    const float* epsb0 = (const float*)d_in[ebg[0]];
    const float* epsb1 = (const float*)d_in[ebg[1]];
    float* out = (float*)d_out;

    probe_kernel<<<1, 32>>>((const float*)d_in[bg[0]], (const float*)d_in[bg[1]],
                            (const float*)d_in[bg[2]], (const float*)d_in[bg[3]],
                            (const float*)d_in[wg[0]], (const float*)d_in[wg[1]],
                            (const float*)d_in[wg[2]], (const float*)d_in[wg[3]]);

    pre_kernel<<<512, 256>>>(out);
    kl_kernel<<<512, 256>>>(out);

    dim3 grid(Hh, 2);
    for (int t = 0; t <= Lq; t++) {
        step_kernel<<<grid, 128>>>(t, x, epsw0, epsb0, epsw1, epsb1, out);
    }
    final_kernel<<<128, 256>>>(out);
}